// round 11
// baseline (speedup 1.0000x reference)
#include <cuda_runtime.h>
#include <cstdint>

#define BS  16
#define NA  33600
#define NG  64
#define NC  80
#define NT1 256
#define ABLK 1024                       // anchors per block
#define KSUB 4                          // ABLK / NT1
#define NCHUNK 33                       // ceil(33600/1024); last block: 832 anchors
#define NCOMP (BS * NCHUNK)             // 528 compute blocks -> single wave

// ---------------- scratch (device globals; no allocation) ----------------
__device__ int g_posAnyBlk[BS * NCHUNK];

__device__ __forceinline__ bool fgt(float n1, float d1, float n2, float d2) {
    return __fmul_rn(n1, d2) > __fmul_rn(n2, d1);
}

__device__ __forceinline__ void ins3(float n, float d,
    float& t0n, float& t0d, float& t1n, float& t1d, float& t2n, float& t2d) {
    if (fgt(n, d, t2n, t2d)) {
        if (fgt(n, d, t1n, t1d)) {
            t2n = t1n; t2d = t1d;
            if (fgt(n, d, t0n, t0d)) { t1n = t0n; t1d = t0d; t0n = n; t0d = d; }
            else                     { t1n = n;   t1d = d; }
        } else { t2n = n; t2d = d; }
    }
}

// ================= main fused kernel: compute + ALL output writes =========
__global__ __launch_bounds__(NT1)
void k1f(const float4* __restrict__ pd,
         const float4* __restrict__ gt,
         const int*    __restrict__ mg,
         const int*    __restrict__ glRaw,
         float*  __restrict__ outLab,
         float4* __restrict__ outBox,
         float*  __restrict__ outFg,
         float*  __restrict__ outTgi,
         float*  __restrict__ outScores) {
    __shared__ float4 sboxc[NG];     // compacted valid boxes
    __shared__ float  sareac[NG];
    __shared__ int    sgidxc[NG];
    __shared__ float4 sbox0[NG];     // original boxes
    __shared__ int    slab[NG];
    __shared__ int    svalid[NG];
    __shared__ int    spacked[ABLK]; // per-anchor lab | mask<<8
    __shared__ int    scnt[2];
    __shared__ int    snv, sl64;
    __shared__ __align__(16) float sbuf[2][64 * NC];   // 2 x 20 KB staging

    const int cb    = blockIdx.x;
    const int b     = cb / NCHUNK;
    const int chunk = cb % NCHUNK;
    const int tid   = threadIdx.x;

    int v = 0; unsigned bm = 0; float4 q;
    if (tid < NG) {
        v = mg[b * NG + tid];
        q = gt[b * NG + tid];
        bm = __ballot_sync(0xffffffffu, v != 0);
        if ((tid & 31) == 0) scnt[tid >> 5] = __popc(bm);
        sbox0[tid]  = q;
        svalid[tid] = v;
    }
    if (tid == 0)
        sl64 = ((glRaw[1] | glRaw[3] | glRaw[5] | glRaw[7] | glRaw[9] | glRaw[11]) == 0);

    // zero both staging buffers (2560 float4, 10 per thread)
    {
        float4* z = (float4*)sbuf;
        #pragma unroll
        for (int i = 0; i < 2 * 64 * NC / 4 / NT1; i++)
            z[tid + i * NT1] = make_float4(0.f, 0.f, 0.f, 0.f);
    }
    __syncthreads();

    if (tid < NG) {
        slab[tid] = sl64 ? (int)((const long long*)glRaw)[b * NG + tid]
                         : glRaw[b * NG + tid];
        if (v) {
            int pos = __popc(bm & ((1u << (tid & 31)) - 1)) + ((tid >= 32) ? scnt[0] : 0);
            sboxc[pos]  = q;
            sareac[pos] = __fmul_rn(__fsub_rn(q.z, q.x), __fsub_rn(q.w, q.y));
            sgidxc[pos] = tid;
        }
        if (tid == 0) snv = scnt[0] + scnt[1];
    }
    __syncthreads();

    const int aBase = chunk * ABLK;
    bool anyPos = false;

    #pragma unroll
    for (int k = 0; k < KSUB; k++) {
        const int a = aBase + k * NT1 + tid;
        int packed = 0;
        if (a < NA) {
            float4 p = pd[b * NA + a];
            float parea = __fmul_rn(__fsub_rn(p.z, p.x), __fsub_rn(p.w, p.y));
            float b0n = 0.f, b0d = 1.f, b1n = 0.f, b1d = 1.f;
            int   i0 = 0, i1 = 0;
            const int nv = snv;
            #pragma unroll 4
            for (int j = 0; j < nv; j++) {
                float4 qq = sboxc[j];
                float iw = fmaxf(__fsub_rn(fminf(qq.z, p.z), fmaxf(qq.x, p.x)), 0.f);
                float ih = fmaxf(__fsub_rn(fminf(qq.w, p.w), fmaxf(qq.y, p.y)), 0.f);
                float num = __fmul_rn(iw, ih);
                float den = __fadd_rn(__fsub_rn(__fadd_rn(sareac[j], parea), num), 1e-9f);
                if (__fmul_rn(num, b1d) > __fmul_rn(b1n, den)) {
                    int g = sgidxc[j];
                    if (__fmul_rn(num, b0d) > __fmul_rn(b0n, den)) {
                        b1n = b0n; b1d = b0d; i1 = i0;
                        b0n = num; b0d = den; i0 = g;
                    } else {
                        b1n = num; b1d = den; i1 = g;
                    }
                }
            }
            float r0 = __fdiv_rn(b0n, b0d);
            float r1 = __fdiv_rn(b1n, b1d);
            int bi = i0;
            if (r1 == r0 && i1 < i0) bi = i1;
            bool posAny = r0 > 0.3f;
            anyPos |= posAny;

            const int idx = b * NA + a;
            bool mask = posAny && (svalid[bi] != 0);
            int  lab  = slab[bi];

            __stcs(&outLab[idx], mask ? (float)lab : (float)NC);
            float4 bx = sbox0[bi];
            __stcs(&outBox[idx], mask ? bx : make_float4(0.f, 0.f, 0.f, 0.f));
            __stcs(&outFg[idx],  posAny ? 1.f : 0.f);
            __stcs(&outTgi[idx], (float)bi);
            packed = lab | (mask ? 0x100 : 0);
        }
        spacked[k * NT1 + tid] = packed;
    }
    int anyBlk = __syncthreads_or(anyPos ? 1 : 0);
    if (tid == 0) g_posAnyBlk[b * NCHUNK + chunk] = anyBlk;

    // ----- stream this block's score rows (zeros + one-hot) via TMA bulk ---
    const int remA    = min(ABLK, NA - aBase);
    const int nChunks = (remA + 63) / 64;           // 16 (13 for last block)
    float* gbase = outScores + ((size_t)b * NA + (size_t)aBase) * NC;
    int prev0 = -1, prev1 = -1;

    for (int c = 0; c < nChunks; c++) {
        int sel = c & 1;
        if (c >= 2 && tid == 0)
            asm volatile("cp.async.bulk.wait_group.read 1;" ::: "memory");
        __syncthreads();                         // buffer[sel] now reusable
        int nA = min(64, remA - c * 64);
        if (tid < 64) {
            int prev = sel ? prev1 : prev0;
            float* buf = sbuf[sel];
            if (prev >= 0) buf[prev] = 0.f;      // clear stale one
            int np = -1;
            if (tid < nA) {
                int p = spacked[c * 64 + tid];
                if (p & 0x100) { np = tid * NC + (p & 0xFF); buf[np] = 1.f; }
            }
            if (sel) prev1 = np; else prev0 = np;
        }
        __syncthreads();
        if (tid == 0) {
            asm volatile("fence.proxy.async.shared::cta;" ::: "memory");
            uint32_t saddr = (uint32_t)__cvta_generic_to_shared(sbuf[sel]);
            float* gdst = gbase + (size_t)c * 64 * NC;
            asm volatile(
                "cp.async.bulk.global.shared::cta.bulk_group [%0], [%1], %2;"
                :: "l"(gdst), "r"(saddr), "r"(nA * NC * 4) : "memory");
            asm volatile("cp.async.bulk.commit_group;" ::: "memory");
        }
    }
    if (tid == 0)
        asm volatile("cp.async.bulk.wait_group 0;" ::: "memory");
    __syncthreads();   // keep smem alive until bulk copies complete
}

// ===== single fallback kernel: decides need_fb itself, one block/batch =====
// Statistically never active beyond the flag check; correctness path only.
__global__ __launch_bounds__(NT1)
void k_fb(const float4* __restrict__ pd,
          const float4* __restrict__ gt,
          const int*    __restrict__ glRaw,
          const int*    __restrict__ mg,
          float*  __restrict__ outLab,
          float4* __restrict__ outBox,
          float*  __restrict__ outFg,
          float*  __restrict__ outTgi,
          float*  __restrict__ outScores) {
    const int b   = blockIdx.x;
    const int tid = threadIdx.x;

    int f  = (tid < NCHUNK) ? g_posAnyBlk[b * NCHUNK + tid] : 0;
    int anyP = __syncthreads_or(f);
    int hv   = __syncthreads_or((tid < NG) ? (mg[b * NG + tid] != 0) : 0);
    if (anyP || !hv) return;   // no fallback needed for this batch

    __shared__ float4 sbox[NG];
    __shared__ float  sqa[NG];
    __shared__ int    svalid[NG];
    __shared__ int    slab[NG];
    __shared__ float  s0n[NT1], s0d[NT1], s1n[NT1], s1d[NT1], s2n[NT1], s2d[NT1];
    __shared__ float  sMinIou;
    __shared__ int    sl64;

    if (tid == 0)
        sl64 = ((glRaw[1] | glRaw[3] | glRaw[5] | glRaw[7] | glRaw[9] | glRaw[11]) == 0);
    __syncthreads();
    if (tid < NG) {
        int v = mg[b * NG + tid];
        float4 q = gt[b * NG + tid];
        if (v == 0) q = make_float4(0.f, 0.f, 0.f, 0.f);
        sbox[tid]   = q;
        sqa[tid]    = __fmul_rn(__fsub_rn(q.z, q.x), __fsub_rn(q.w, q.y));
        svalid[tid] = v;
        slab[tid]   = sl64 ? (int)((const long long*)glRaw)[b * NG + tid]
                           : glRaw[b * NG + tid];
    }
    __syncthreads();

    // -------- phase 1: batch-wide top-3 over valid GT fractions --------
    float t0n = -1.f, t0d = 1.f, t1n = -1.f, t1d = 1.f, t2n = -1.f, t2d = 1.f;
    for (int a = tid; a < NA; a += NT1) {
        float4 p = pd[b * NA + a];
        float parea = __fmul_rn(__fsub_rn(p.z, p.x), __fsub_rn(p.w, p.y));
        for (int g = 0; g < NG; g++) {
            if (!svalid[g]) continue;
            float4 q = sbox[g];
            float iw = fmaxf(__fsub_rn(fminf(q.z, p.z), fmaxf(q.x, p.x)), 0.f);
            float ih = fmaxf(__fsub_rn(fminf(q.w, p.w), fmaxf(q.y, p.y)), 0.f);
            float num = __fmul_rn(iw, ih);
            float den = __fadd_rn(__fsub_rn(__fadd_rn(sqa[g], parea), num), 1e-9f);
            ins3(num, den, t0n, t0d, t1n, t1d, t2n, t2d);
        }
    }
    s0n[tid] = t0n; s0d[tid] = t0d;
    s1n[tid] = t1n; s1d[tid] = t1d;
    s2n[tid] = t2n; s2d[tid] = t2d;
    __syncthreads();
    for (int off = NT1 / 2; off > 0; off >>= 1) {
        if (tid < off) {
            float m0n = s0n[tid], m0d = s0d[tid], m1n = s1n[tid], m1d = s1d[tid],
                  m2n = s2n[tid], m2d = s2d[tid];
            int j = tid + off;
            ins3(s0n[j], s0d[j], m0n, m0d, m1n, m1d, m2n, m2d);
            ins3(s1n[j], s1d[j], m0n, m0d, m1n, m1d, m2n, m2d);
            ins3(s2n[j], s2d[j], m0n, m0d, m1n, m1d, m2n, m2d);
            s0n[tid] = m0n; s0d[tid] = m0d;
            s1n[tid] = m1n; s1d[tid] = m1d;
            s2n[tid] = m2n; s2d[tid] = m2d;
        }
        __syncthreads();
    }
    if (tid == 0) sMinIou = __fdiv_rn(s2n[0], s2d[0]);
    __syncthreads();
    const float minIou = sMinIou;

    // -------- phase 2: recompute argmax, rewrite all outputs --------
    for (int a = tid; a < NA; a += NT1) {
        float4 p = pd[b * NA + a];
        float parea = __fmul_rn(__fsub_rn(p.z, p.x), __fsub_rn(p.w, p.y));
        float b0n = 0.f, b0d = 1.f, b1n = 0.f, b1d = 1.f;
        int   i0 = 0, i1 = 0;
        for (int g = 0; g < NG; g++) {
            float4 q = sbox[g];
            float iw = fmaxf(__fsub_rn(fminf(q.z, p.z), fmaxf(q.x, p.x)), 0.f);
            float ih = fmaxf(__fsub_rn(fminf(q.w, p.w), fmaxf(q.y, p.y)), 0.f);
            float num = __fmul_rn(iw, ih);
            float den = __fadd_rn(__fsub_rn(__fadd_rn(sqa[g], parea), num), 1e-9f);
            if (__fmul_rn(num, b1d) > __fmul_rn(b1n, den)) {
                if (__fmul_rn(num, b0d) > __fmul_rn(b0n, den)) {
                    b1n = b0n; b1d = b0d; i1 = i0;
                    b0n = num; b0d = den; i0 = g;
                } else {
                    b1n = num; b1d = den; i1 = g;
                }
            }
        }
        float r0 = __fdiv_rn(b0n, b0d);
        float r1 = __fdiv_rn(b1n, b1d);
        int tgi = i0;
        if (r1 == r0 && i1 < i0) tgi = i1;

        const int idx = b * NA + a;
        bool fg   = r0 >= minIou;
        bool va   = svalid[tgi] != 0;
        bool mask = fg && va;
        int  lab  = slab[tgi];

        outLab[idx] = mask ? (float)lab : (float)NC;
        float4 bx = gt[b * NG + tgi];
        outBox[idx] = mask ? bx : make_float4(0.f, 0.f, 0.f, 0.f);
        outFg[idx]  = fg ? 1.f : 0.f;
        outTgi[idx] = (float)tgi;
        if (mask) outScores[(size_t)idx * NC + lab] = 1.f;  // row is all-zero
    }
}

// ------------------------------ entry point -------------------------------
// inputs: 0 pd_scores, 1 pd_bboxes, 2 anc_points, 3 gt_labels, 4 gt_bboxes, 5 mask_gt
// output: float32 concat [labels | bboxes | scores | fg_mask | tgi]
extern "C" void kernel_launch(void* const* d_in, const int* in_sizes, int n_in,
                              void* d_out, int out_size) {
    const float4* pd = (const float4*)d_in[1];
    const int*    gl = (const int*)d_in[3];
    const float4* gt = (const float4*)d_in[4];
    const int*    mg = (const int*)d_in[5];

    float* out = (float*)d_out;
    const size_t E = (size_t)BS * NA;
    float*  outLab    = out;
    float4* outBox    = (float4*)(out + E);
    float*  outScores = out + E * 5;
    float*  outFg     = out + E * 85;
    float*  outTgi    = out + E * 86;

    k1f<<<NCOMP, NT1>>>(pd, gt, mg, gl, outLab, outBox, outFg, outTgi, outScores);
    k_fb<<<BS, NT1>>>(pd, gt, gl, mg, outLab, outBox, outFg, outTgi, outScores);
}

// round 13
// speedup vs baseline: 1.3721x; 1.3721x over previous
#include <cuda_runtime.h>
#include <cstdint>

#define BS  16
#define NA  33600
#define NG  64
#define NC  80
#define NT1 256
#define NCHUNK 132                      // ceil(33600/256); last chunk has 64 anchors
#define NCOMP (BS * NCHUNK)             // 2112 compute blocks

// ---------------- scratch (device globals; no allocation) ----------------
__device__ int g_posAnyBlk[BS * NCHUNK];

__device__ __forceinline__ bool fgt(float n1, float d1, float n2, float d2) {
    return __fmul_rn(n1, d2) > __fmul_rn(n2, d1);
}

__device__ __forceinline__ void ins3(float n, float d,
    float& t0n, float& t0d, float& t1n, float& t1d, float& t2n, float& t2d) {
    if (fgt(n, d, t2n, t2d)) {
        if (fgt(n, d, t1n, t1d)) {
            t2n = t1n; t2d = t1d;
            if (fgt(n, d, t0n, t0d)) { t1n = t0n; t1d = t0d; t0n = n; t0d = d; }
            else                     { t1n = n;   t1d = d; }
        } else { t2n = n; t2d = d; }
    }
}

// ================= main fused kernel: compute + ALL output writes =========
// The 80 KB score span per block is zero except one 1.0 per fg anchor.
// A single 20 KB zero buffer is TMA-bulk-copied 4x, issued BEFORE the compute
// (TMA overlaps the IoU loop); sparse ones are fixed up with STG afterward.
__global__ __launch_bounds__(NT1)
void k1f(const float4* __restrict__ pd,
         const float4* __restrict__ gt,
         const int*    __restrict__ mg,
         const int*    __restrict__ glRaw,
         float*  __restrict__ outLab,
         float4* __restrict__ outBox,
         float*  __restrict__ outFg,
         float*  __restrict__ outTgi,
         float*  __restrict__ outScores) {
    __shared__ float4 sboxc[NG];     // compacted valid boxes
    __shared__ float  sareac[NG];
    __shared__ int    sgidxc[NG];
    __shared__ float4 sbox0[NG];     // original boxes
    __shared__ int    slab[NG];
    __shared__ int    svalid[NG];
    __shared__ int    scnt[2];
    __shared__ int    snv, sl64;
    __shared__ __align__(16) float4 szero4[64 * NC / 4];  // 20 KB zero buffer

    const int cb    = blockIdx.x;
    const int b     = cb / NCHUNK;
    const int chunk = cb % NCHUNK;
    const int tid   = threadIdx.x;

    int v = 0; unsigned bm = 0; float4 q;
    if (tid < NG) {
        v = mg[b * NG + tid];
        q = gt[b * NG + tid];
        bm = __ballot_sync(0xffffffffu, v != 0);
        if ((tid & 31) == 0) scnt[tid >> 5] = __popc(bm);
        sbox0[tid]  = q;
        svalid[tid] = v;
    }
    if (tid == 0)
        sl64 = ((glRaw[1] | glRaw[3] | glRaw[5] | glRaw[7] | glRaw[9] | glRaw[11]) == 0);

    // zero the TMA source buffer once (5 float4 per thread)
    #pragma unroll
    for (int i = 0; i < 64 * NC / 4 / NT1; i++)
        szero4[tid + i * NT1] = make_float4(0.f, 0.f, 0.f, 0.f);

    __syncthreads();   // scnt/szero4 visible before compaction reads scnt[0]

    if (tid < NG) {
        slab[tid] = sl64 ? (int)((const long long*)glRaw)[b * NG + tid]
                         : glRaw[b * NG + tid];
        if (v) {
            int pos = __popc(bm & ((1u << (tid & 31)) - 1)) + ((tid >= 32) ? scnt[0] : 0);
            sboxc[pos]  = q;
            sareac[pos] = __fmul_rn(__fsub_rn(q.z, q.x), __fsub_rn(q.w, q.y));
            sgidxc[pos] = tid;
        }
        if (tid == 0) snv = scnt[0] + scnt[1];
    }
    __syncthreads();

    // ---- issue ALL zero-copies up front: TMA overlaps the compute below ---
    const int aBase = chunk * NT1;
    const int remA  = min(NT1, NA - aBase);
    const int nCp   = (remA + 63) / 64;             // 4 (1 for last chunk)
    if (tid == 0) {
        asm volatile("fence.proxy.async.shared::cta;" ::: "memory");
        uint32_t saddr = (uint32_t)__cvta_generic_to_shared(szero4);
        float* gbase = outScores + ((size_t)b * NA + (size_t)aBase) * NC;
        for (int c = 0; c < nCp; c++) {
            int nA = min(64, remA - c * 64);
            asm volatile(
                "cp.async.bulk.global.shared::cta.bulk_group [%0], [%1], %2;"
                :: "l"(gbase + (size_t)c * 64 * NC), "r"(saddr),
                   "r"(nA * NC * 4) : "memory");
        }
        asm volatile("cp.async.bulk.commit_group;" ::: "memory");
    }

    // --------------------------- compute ----------------------------------
    const int a = aBase + tid;
    bool posAny = false;
    int  packed = 0;

    if (a < NA) {
        float4 p = pd[b * NA + a];
        float parea = __fmul_rn(__fsub_rn(p.z, p.x), __fsub_rn(p.w, p.y));
        float b0n = 0.f, b0d = 1.f, b1n = 0.f, b1d = 1.f;
        int   i0 = 0, i1 = 0;
        const int nv = snv;
        #pragma unroll 4
        for (int j = 0; j < nv; j++) {
            float4 qq = sboxc[j];
            float iw = fmaxf(__fsub_rn(fminf(qq.z, p.z), fmaxf(qq.x, p.x)), 0.f);
            float ih = fmaxf(__fsub_rn(fminf(qq.w, p.w), fmaxf(qq.y, p.y)), 0.f);
            float num = __fmul_rn(iw, ih);
            float den = __fadd_rn(__fsub_rn(__fadd_rn(sareac[j], parea), num), 1e-9f);
            if (__fmul_rn(num, b1d) > __fmul_rn(b1n, den)) {
                int g = sgidxc[j];
                if (__fmul_rn(num, b0d) > __fmul_rn(b0n, den)) {
                    b1n = b0n; b1d = b0d; i1 = i0;
                    b0n = num; b0d = den; i0 = g;
                } else {
                    b1n = num; b1d = den; i1 = g;
                }
            }
        }
        float r0 = __fdiv_rn(b0n, b0d);
        float r1 = __fdiv_rn(b1n, b1d);
        int bi = i0;
        if (r1 == r0 && i1 < i0) bi = i1;
        posAny = r0 > 0.3f;

        const int idx = b * NA + a;
        bool mask = posAny && (svalid[bi] != 0);
        int  lab  = slab[bi];

        __stcs(&outLab[idx], mask ? (float)lab : (float)NC);
        float4 bx = sbox0[bi];
        __stcs(&outBox[idx], mask ? bx : make_float4(0.f, 0.f, 0.f, 0.f));
        __stcs(&outFg[idx],  posAny ? 1.f : 0.f);
        __stcs(&outTgi[idx], (float)bi);
        packed = lab | (mask ? 0x100 : 0);
    }
    int anyBlk = __syncthreads_or(posAny ? 1 : 0);
    if (tid == 0) g_posAnyBlk[b * NCHUNK + chunk] = anyBlk;

    // ---- wait for zero-copies, then scatter the sparse ones ---------------
    if (tid == 0)
        asm volatile("cp.async.bulk.wait_group 0;" ::: "memory");
    __syncthreads();                     // TMA zeros complete & visible
    if (packed & 0x100) {
        const int idx = b * NA + a;
        outScores[(size_t)idx * NC + (packed & 0xFF)] = 1.f;
    }
}

// ===== single fallback kernel: decides need_fb itself, one block/batch =====
// Statistically never active beyond the flag check; correctness path only.
__global__ __launch_bounds__(NT1)
void k_fb(const float4* __restrict__ pd,
          const float4* __restrict__ gt,
          const int*    __restrict__ glRaw,
          const int*    __restrict__ mg,
          float*  __restrict__ outLab,
          float4* __restrict__ outBox,
          float*  __restrict__ outFg,
          float*  __restrict__ outTgi,
          float*  __restrict__ outScores) {
    const int b   = blockIdx.x;
    const int tid = threadIdx.x;

    int f  = (tid < NCHUNK) ? g_posAnyBlk[b * NCHUNK + tid] : 0;
    int anyP = __syncthreads_or(f);
    int hv   = __syncthreads_or((tid < NG) ? (mg[b * NG + tid] != 0) : 0);
    if (anyP || !hv) return;   // no fallback needed for this batch

    __shared__ float4 sbox[NG];
    __shared__ float  sqa[NG];
    __shared__ int    svalid[NG];
    __shared__ int    slab[NG];
    __shared__ float  s0n[NT1], s0d[NT1], s1n[NT1], s1d[NT1], s2n[NT1], s2d[NT1];
    __shared__ float  sMinIou;
    __shared__ int    sl64;

    if (tid == 0)
        sl64 = ((glRaw[1] | glRaw[3] | glRaw[5] | glRaw[7] | glRaw[9] | glRaw[11]) == 0);
    __syncthreads();
    if (tid < NG) {
        int v = mg[b * NG + tid];
        float4 q = gt[b * NG + tid];
        if (v == 0) q = make_float4(0.f, 0.f, 0.f, 0.f);
        sbox[tid]   = q;
        sqa[tid]    = __fmul_rn(__fsub_rn(q.z, q.x), __fsub_rn(q.w, q.y));
        svalid[tid] = v;
        slab[tid]   = sl64 ? (int)((const long long*)glRaw)[b * NG + tid]
                           : glRaw[b * NG + tid];
    }
    __syncthreads();

    // -------- phase 1: batch-wide top-3 over valid GT fractions --------
    float t0n = -1.f, t0d = 1.f, t1n = -1.f, t1d = 1.f, t2n = -1.f, t2d = 1.f;
    for (int a = tid; a < NA; a += NT1) {
        float4 p = pd[b * NA + a];
        float parea = __fmul_rn(__fsub_rn(p.z, p.x), __fsub_rn(p.w, p.y));
        for (int g = 0; g < NG; g++) {
            if (!svalid[g]) continue;
            float4 q = sbox[g];
            float iw = fmaxf(__fsub_rn(fminf(q.z, p.z), fmaxf(q.x, p.x)), 0.f);
            float ih = fmaxf(__fsub_rn(fminf(q.w, p.w), fmaxf(q.y, p.y)), 0.f);
            float num = __fmul_rn(iw, ih);
            float den = __fadd_rn(__fsub_rn(__fadd_rn(sqa[g], parea), num), 1e-9f);
            ins3(num, den, t0n, t0d, t1n, t1d, t2n, t2d);
        }
    }
    s0n[tid] = t0n; s0d[tid] = t0d;
    s1n[tid] = t1n; s1d[tid] = t1d;
    s2n[tid] = t2n; s2d[tid] = t2d;
    __syncthreads();
    for (int off = NT1 / 2; off > 0; off >>= 1) {
        if (tid < off) {
            float m0n = s0n[tid], m0d = s0d[tid], m1n = s1n[tid], m1d = s1d[tid],
                  m2n = s2n[tid], m2d = s2d[tid];
            int j = tid + off;
            ins3(s0n[j], s0d[j], m0n, m0d, m1n, m1d, m2n, m2d);
            ins3(s1n[j], s1d[j], m0n, m0d, m1n, m1d, m2n, m2d);
            ins3(s2n[j], s2d[j], m0n, m0d, m1n, m1d, m2n, m2d);
            s0n[tid] = m0n; s0d[tid] = m0d;
            s1n[tid] = m1n; s1d[tid] = m1d;
            s2n[tid] = m2n; s2d[tid] = m2d;
        }
        __syncthreads();
    }
    if (tid == 0) sMinIou = __fdiv_rn(s2n[0], s2d[0]);
    __syncthreads();
    const float minIou = sMinIou;

    // -------- phase 2: recompute argmax, rewrite all outputs --------
    for (int a = tid; a < NA; a += NT1) {
        float4 p = pd[b * NA + a];
        float parea = __fmul_rn(__fsub_rn(p.z, p.x), __fsub_rn(p.w, p.y));
        float b0n = 0.f, b0d = 1.f, b1n = 0.f, b1d = 1.f;
        int   i0 = 0, i1 = 0;
        for (int g = 0; g < NG; g++) {
            float4 q = sbox[g];
            float iw = fmaxf(__fsub_rn(fminf(q.z, p.z), fmaxf(q.x, p.x)), 0.f);
            float ih = fmaxf(__fsub_rn(fminf(q.w, p.w), fmaxf(q.y, p.y)), 0.f);
            float num = __fmul_rn(iw, ih);
            float den = __fadd_rn(__fsub_rn(__fadd_rn(sqa[g], parea), num), 1e-9f);
            if (__fmul_rn(num, b1d) > __fmul_rn(b1n, den)) {
                if (__fmul_rn(num, b0d) > __fmul_rn(b0n, den)) {
                    b1n = b0n; b1d = b0d; i1 = i0;
                    b0n = num; b0d = den; i0 = g;
                } else {
                    b1n = num; b1d = den; i1 = g;
                }
            }
        }
        float r0 = __fdiv_rn(b0n, b0d);
        float r1 = __fdiv_rn(b1n, b1d);
        int tgi = i0;
        if (r1 == r0 && i1 < i0) tgi = i1;

        const int idx = b * NA + a;
        bool fg   = r0 >= minIou;
        bool va   = svalid[tgi] != 0;
        bool mask = fg && va;
        int  lab  = slab[tgi];

        outLab[idx] = mask ? (float)lab : (float)NC;
        float4 bx = gt[b * NG + tgi];
        outBox[idx] = mask ? bx : make_float4(0.f, 0.f, 0.f, 0.f);
        outFg[idx]  = fg ? 1.f : 0.f;
        outTgi[idx] = (float)tgi;
        if (mask) outScores[(size_t)idx * NC + lab] = 1.f;  // row is all-zero
    }
}

// ------------------------------ entry point -------------------------------
// inputs: 0 pd_scores, 1 pd_bboxes, 2 anc_points, 3 gt_labels, 4 gt_bboxes, 5 mask_gt
// output: float32 concat [labels | bboxes | scores | fg_mask | tgi]
extern "C" void kernel_launch(void* const* d_in, const int* in_sizes, int n_in,
                              void* d_out, int out_size) {
    const float4* pd = (const float4*)d_in[1];
    const int*    gl = (const int*)d_in[3];
    const float4* gt = (const float4*)d_in[4];
    const int*    mg = (const int*)d_in[5];

    float* out = (float*)d_out;
    const size_t E = (size_t)BS * NA;
    float*  outLab    = out;
    float4* outBox    = (float4*)(out + E);
    float*  outScores = out + E * 5;
    float*  outFg     = out + E * 85;
    float*  outTgi    = out + E * 86;

    k1f<<<NCOMP, NT1>>>(pd, gt, mg, gl, outLab, outBox, outFg, outTgi, outScores);
    k_fb<<<BS, NT1>>>(pd, gt, gl, mg, outLab, outBox, outFg, outTgi, outScores);
}